// round 1
// baseline (speedup 1.0000x reference)
#include <cuda_runtime.h>

// GRU sequence encoder: final hidden state per sequence.
// N=16384 sequences, L=512, ES=32, HS=64, gates stacked [r|z|n] (torch order).
//
// Design: persistent CTAs (192 threads) with a global atomic work queue.
// Thread j in [0,192) owns stacked gate-row j; its 96 weights live in
// registers for the CTA's whole lifetime. One sequence at a time per CTA
// (zero padding waste: loop breaks at first zero token == length mask).
// Matvec operands (e[32], h[64]) are broadcast LDS reads.

#define N_SEQ   16384
#define L_SEQ   512
#define ES_DIM  32
#define HS_DIM  64
#define G3      192   // 3 * HS

__device__ int g_next_seq;

__global__ void init_counter_kernel() {
    g_next_seq = 0;
}

__launch_bounds__(192, 2)
__global__ void gru_encode_kernel(const int*   __restrict__ x,
                                  const float* __restrict__ emb,
                                  const float* __restrict__ w_ih,
                                  const float* __restrict__ w_hh,
                                  const float* __restrict__ b_ih,
                                  const float* __restrict__ b_hh,
                                  float*       __restrict__ out)
{
    __shared__ float4 e_sm4[ES_DIM / 4];     // embedding row of current token
    __shared__ float4 h_sm4[HS_DIM / 4];     // hidden state
    __shared__ float  gate_sm[G3 + HS_DIM];  // r[0:64) z[64:128) xn[128:192) hn[192:256)
    __shared__ int    seq_sm;

    float* e_sm = reinterpret_cast<float*>(e_sm4);
    float* h_sm = reinterpret_cast<float*>(h_sm4);

    const int j = threadIdx.x;  // 0..191 = stacked gate row

    // ---- load this thread's weight rows into registers (once per CTA) ----
    float wih[ES_DIM];
    {
        const float4* wr = reinterpret_cast<const float4*>(w_ih + (long)j * ES_DIM);
        #pragma unroll
        for (int k = 0; k < ES_DIM / 4; k++) {
            float4 v = wr[k];
            wih[4*k+0] = v.x; wih[4*k+1] = v.y; wih[4*k+2] = v.z; wih[4*k+3] = v.w;
        }
    }
    float whh[HS_DIM];
    {
        const float4* wr = reinterpret_cast<const float4*>(w_hh + (long)j * HS_DIM);
        #pragma unroll
        for (int k = 0; k < HS_DIM / 4; k++) {
            float4 v = wr[k];
            whh[4*k+0] = v.x; whh[4*k+1] = v.y; whh[4*k+2] = v.z; whh[4*k+3] = v.w;
        }
    }
    const float bih = b_ih[j];
    const float bhh = b_hh[j];
    const bool  is_n = (j >= 2 * HS_DIM);
    const float bias_rz = bih + bhh;  // r,z gates: biases combine

    while (true) {
        if (j == 0) seq_sm = atomicAdd(&g_next_seq, 1);
        __syncthreads();
        const int seq = seq_sm;
        if (seq >= N_SEQ) break;   // uniform across CTA

        // zero hidden state (visible at first in-loop barrier)
        if (j < HS_DIM) h_sm[j] = 0.0f;

        const int* xrow = x + (long)seq * L_SEQ;

        for (int t = 0; t < L_SEQ; t++) {
            const int tok = __ldg(&xrow[t]);   // same address all threads (broadcast)
            if (tok == 0) break;               // uniform: zeros only pad the tail

            // gather embedding row for this token
            if (j < ES_DIM / 4) {
                e_sm4[j] = reinterpret_cast<const float4*>(emb + (long)tok * ES_DIM)[j];
            }
            __syncthreads();  // e ready; h (prev update / init) ready

            // ---- matvec: acc_e = e . wih_row(j), acc_h = h . whh_row(j) ----
            float a0 = 0.f, a1 = 0.f, a2 = 0.f, a3 = 0.f;
            #pragma unroll
            for (int k = 0; k < ES_DIM / 4; k++) {
                float4 e = e_sm4[k];
                a0 = fmaf(wih[4*k+0], e.x, a0);
                a1 = fmaf(wih[4*k+1], e.y, a1);
                a2 = fmaf(wih[4*k+2], e.z, a2);
                a3 = fmaf(wih[4*k+3], e.w, a3);
            }
            const float acc_e = (a0 + a1) + (a2 + a3);

            float b0 = 0.f, b1 = 0.f, b2 = 0.f, b3 = 0.f;
            #pragma unroll
            for (int k = 0; k < HS_DIM / 4; k++) {
                float4 h = h_sm4[k];
                b0 = fmaf(whh[4*k+0], h.x, b0);
                b1 = fmaf(whh[4*k+1], h.y, b1);
                b2 = fmaf(whh[4*k+2], h.z, b2);
                b3 = fmaf(whh[4*k+3], h.w, b3);
            }
            const float acc_h = (b0 + b1) + (b2 + b3);

            if (!is_n) {
                gate_sm[j] = acc_e + acc_h + bias_rz;     // r or z pre-activation
            } else {
                gate_sm[j]          = acc_e + bih;        // xn  at [128:192)
                gate_sm[j + HS_DIM] = acc_h + bhh;        // hn  at [192:256)
            }
            __syncthreads();  // gates ready; all matvec reads of e,h done

            // ---- gate nonlinearities + hidden update (threads 0..63) ----
            if (j < HS_DIM) {
                const float gr = gate_sm[j];
                const float gz = gate_sm[HS_DIM + j];
                const float xn = gate_sm[2 * HS_DIM + j];
                const float hn = gate_sm[3 * HS_DIM + j];
                const float r  = __fdividef(1.0f, 1.0f + __expf(-gr));
                const float z  = __fdividef(1.0f, 1.0f + __expf(-gz));
                const float a  = xn + r * hn;
                // tanh(a) = 1 - 2/(e^{2a}+1); saturates correctly at +/-inf
                const float ng = 1.0f - __fdividef(2.0f, __expf(2.0f * a) + 1.0f);
                const float h_old = h_sm[j];
                h_sm[j] = (1.0f - z) * ng + z * h_old;
            }
            // no barrier here: next iteration's barrier (after gather)
            // publishes the h update before anyone reads h again.
        }

        __syncthreads();  // final h update visible
        if (j < HS_DIM) {
            out[(long)seq * HS_DIM + j] = h_sm[j];  // zero-length seqs -> zeros
        }
        // next claim's barrier orders h_sm reuse
    }
}

extern "C" void kernel_launch(void* const* d_in, const int* in_sizes, int n_in,
                              void* d_out, int out_size)
{
    const int*   x    = (const int*)  d_in[0];
    const float* emb  = (const float*)d_in[1];
    const float* w_ih = (const float*)d_in[2];
    const float* w_hh = (const float*)d_in[3];
    const float* b_ih = (const float*)d_in[4];
    const float* b_hh = (const float*)d_in[5];
    float*       out  = (float*)d_out;

    init_counter_kernel<<<1, 1>>>();
    gru_encode_kernel<<<592, 192>>>(x, emb, w_ih, w_hh, b_ih, b_hh, out);
}

// round 2
// speedup vs baseline: 2.7893x; 2.7893x over previous
#include <cuda_runtime.h>

// GRU sequence encoder, round 2.
// N=16384, L=512, ES=32, HS=64, gates [r|z|n] (torch order).
//
// Pipeline: zero -> lengths+histogram -> suffix-scan -> scatter (counting sort
// by length, descending) -> persistent main kernel, 8 sequences per CTA group
// (near-equal lengths), packed fma.rn.f32x2 matvec, weights in registers.

#define N_SEQ   16384
#define L_SEQ   512
#define ES_DIM  32
#define HS_DIM  64
#define WG      8            // sequences per group
#define NGROUP  (N_SEQ / WG) // 2048
#define NBUCKET 513

__device__ int d_len[N_SEQ];
__device__ int d_bucket[NBUCKET];
__device__ int d_off[NBUCKET];
__device__ int d_sorted[N_SEQ];
__device__ int g_ctr;

// packed dual-fp32 FMA (Blackwell): acc.lo += a.lo*b.lo, acc.hi += a.hi*b.hi
#define FFMA2(acc, a, b) \
    asm("fma.rn.f32x2 %0, %1, %2, %0;" : "+l"(acc) : "l"(a), "l"(b))

__device__ __forceinline__ float pairsum(unsigned long long v) {
    return __uint_as_float((unsigned)v) + __uint_as_float((unsigned)(v >> 32));
}

// ---------------- prepass kernels ----------------

__global__ void zero_kernel() {
    int t = threadIdx.x;
    if (t < NBUCKET) d_bucket[t] = 0;
    if (t == NBUCKET) g_ctr = 0;
}

// one warp per sequence: count nonzero tokens, histogram
__global__ void len_kernel(const int* __restrict__ x) {
    int seq  = blockIdx.x * 8 + (threadIdx.x >> 5);
    int lane = threadIdx.x & 31;
    const int4* row = reinterpret_cast<const int4*>(x + (long)seq * L_SEQ);
    int c = 0;
    #pragma unroll
    for (int k = 0; k < 4; k++) {
        int4 v = row[lane + 32 * k];
        c += (v.x != 0) + (v.y != 0) + (v.z != 0) + (v.w != 0);
    }
    #pragma unroll
    for (int off = 16; off > 0; off >>= 1) c += __shfl_xor_sync(~0u, c, off);
    if (lane == 0) {
        d_len[seq] = c;
        atomicAdd(&d_bucket[c], 1);
    }
}

// descending suffix scan: d_off[l] = #seqs with length > l
__global__ void scan_kernel() {
    __shared__ int sb[NBUCKET], so[NBUCKET];
    int t = threadIdx.x;
    for (int i = t; i < NBUCKET; i += blockDim.x) sb[i] = d_bucket[i];
    __syncthreads();
    if (t == 0) {
        int run = 0;
        for (int l = NBUCKET - 1; l >= 0; l--) { so[l] = run; run += sb[l]; }
    }
    __syncthreads();
    for (int i = t; i < NBUCKET; i += blockDim.x) d_off[i] = so[i];
}

__global__ void scatter_kernel() {
    int seq = blockIdx.x * blockDim.x + threadIdx.x;
    if (seq >= N_SEQ) return;
    int l = d_len[seq];
    int pos = atomicAdd(&d_off[l], 1);
    d_sorted[pos] = seq;
}

// ---------------- main kernel ----------------

__launch_bounds__(192, 2)
__global__ void gru_main(const int*   __restrict__ x,
                         const float* __restrict__ emb,
                         const float* __restrict__ w_ih,
                         const float* __restrict__ w_hh,
                         const float* __restrict__ b_ih,
                         const float* __restrict__ b_hh,
                         float*       __restrict__ out)
{
    __shared__ int4   tok4[WG][L_SEQ / 4];          // 16 KB: group token rows
    __shared__ float4 ebuf[2][WG][ES_DIM / 4];      // 2 KB : double-buffered e
    __shared__ float4 h4[WG][HS_DIM / 4];           // 2 KB : hidden states
    __shared__ float  gate[4][WG][HS_DIM];          // 8 KB : r,z,xn,hn
    __shared__ int    seq_sm[WG], len_sm[WG], gid_sm;

    const int j = threadIdx.x;          // 0..191 = stacked gate row
    const int i = j & 63;
    const int gsel = j >> 6;            // 0=r, 1=z, 2=n

    // weight rows in registers, pre-packed as 64-bit (2-float) lanes along K
    ulonglong2 wih[ES_DIM / 4];
    {
        const ulonglong2* wp = reinterpret_cast<const ulonglong2*>(w_ih + (long)j * ES_DIM);
        #pragma unroll
        for (int k = 0; k < ES_DIM / 4; k++) wih[k] = wp[k];
    }
    ulonglong2 whh[HS_DIM / 4];
    {
        const ulonglong2* wp = reinterpret_cast<const ulonglong2*>(w_hh + (long)j * HS_DIM);
        #pragma unroll
        for (int k = 0; k < HS_DIM / 4; k++) whh[k] = wp[k];
    }
    const float bih = b_ih[j];
    const float bhh = b_hh[j];
    const float bias_rz = bih + bhh;

    const float4* emb4 = reinterpret_cast<const float4*>(emb);
    const int4*   x4   = reinterpret_cast<const int4*>(x);

    while (true) {
        if (j == 0) gid_sm = atomicAdd(&g_ctr, 1);
        __syncthreads();
        const int g = gid_sm;
        if (g >= NGROUP) break;

        if (j < WG) {
            int s = d_sorted[g * WG + j];
            seq_sm[j] = s;
            len_sm[j] = d_len[s];
        }
        __syncthreads();

        // preload all group tokens (coalesced int4)
        for (int idx = j; idx < WG * (L_SEQ / 4); idx += 192) {
            int s = idx >> 7, k = idx & 127;
            tok4[s][k] = x4[(long)seq_sm[s] * (L_SEQ / 4) + k];
        }
        // zero hidden states (WG*16 = 128 float4)
        if (j < WG * (HS_DIM / 4)) {
            reinterpret_cast<float4*>(h4)[j] = make_float4(0.f, 0.f, 0.f, 0.f);
        }
        __syncthreads();

        const int maxlen = len_sm[0];   // descending sort -> slot 0 is max

        // prologue: gather e(0)
        if (j < 64) {
            int s = j >> 3, k = j & 7;
            int tok = reinterpret_cast<const int*>(tok4[s])[0];
            ebuf[0][s][k] = emb4[(long)tok * 8 + k];
        }
        __syncthreads();   // B1 for t=0

        int p = 0;
        for (int t = 0; t < maxlen; t++) {
            // prefetch e(t+1) into registers (overlaps matvec)
            float4 ef;
            if (j < 64) {
                int s = j >> 3, k = j & 7;
                int tn = (t + 1 < L_SEQ) ? t + 1 : L_SEQ - 1;
                int tok = reinterpret_cast<const int*>(tok4[s])[tn];
                ef = emb4[(long)tok * 8 + k];
            }

            // matvec: 8 sequences, packed-pair FMAs
            #pragma unroll
            for (int s = 0; s < WG; s++) {
                unsigned long long ae = 0ull, ah = 0ull;
                const ulonglong2* ep = reinterpret_cast<const ulonglong2*>(&ebuf[p][s][0]);
                #pragma unroll
                for (int k = 0; k < ES_DIM / 4; k++) {
                    ulonglong2 ev = ep[k];
                    FFMA2(ae, wih[k].x, ev.x);
                    FFMA2(ae, wih[k].y, ev.y);
                }
                const ulonglong2* hp = reinterpret_cast<const ulonglong2*>(&h4[s][0]);
                #pragma unroll
                for (int k = 0; k < HS_DIM / 4; k++) {
                    ulonglong2 hv = hp[k];
                    FFMA2(ah, whh[k].x, hv.x);
                    FFMA2(ah, whh[k].y, hv.y);
                }
                float ge = pairsum(ae);
                float gh = pairsum(ah);
                if (gsel < 2) {
                    gate[gsel][s][i] = ge + gh + bias_rz;   // r or z pre-act
                } else {
                    gate[2][s][i] = ge + bih;               // xn
                    gate[3][s][i] = gh + bhh;               // hn
                }
            }
            __syncthreads();   // B2: gates ready, e/h reads done

            // stash prefetched e for next step (other buffer, no reader yet)
            if (j < 64) {
                int s = j >> 3, k = j & 7;
                ebuf[1 - p][s][k] = ef;
            }

            // update: 512 h-elements over threads 0..127, 4 each
            if (j < 128) {
                #pragma unroll
                for (int q = 0; q < 4; q++) {
                    int u = j + 128 * q;
                    int s = u >> 6, ii = u & 63;
                    float rp = gate[0][s][ii];
                    float zp = gate[1][s][ii];
                    float xn = gate[2][s][ii];
                    float hn = gate[3][s][ii];
                    float r = __fdividef(1.0f, 1.0f + __expf(-rp));
                    float z = __fdividef(1.0f, 1.0f + __expf(-zp));
                    float a = fmaf(r, hn, xn);
                    float ng = 1.0f - __fdividef(2.0f, __expf(2.0f * a) + 1.0f);
                    float* hptr = reinterpret_cast<float*>(h4[s]) + ii;
                    float ho = *hptr;
                    float hnew = fmaf(z, ho - ng, ng);     // (1-z)*ng + z*ho
                    *hptr = (t < len_sm[s]) ? hnew : ho;
                }
            }
            __syncthreads();   // B1: h + e(t+1) published
            p ^= 1;
        }

        // write outputs (zero-length seqs emit the zeroed h)
        if (j < 128) {
            #pragma unroll
            for (int q = 0; q < 4; q++) {
                int u = j + 128 * q;
                int s = u >> 6, ii = u & 63;
                out[(long)seq_sm[s] * HS_DIM + ii] =
                    reinterpret_cast<const float*>(h4[s])[ii];
            }
        }
        // claim barrier at loop top orders smem reuse
    }
}

extern "C" void kernel_launch(void* const* d_in, const int* in_sizes, int n_in,
                              void* d_out, int out_size)
{
    const int*   x    = (const int*)  d_in[0];
    const float* emb  = (const float*)d_in[1];
    const float* w_ih = (const float*)d_in[2];
    const float* w_hh = (const float*)d_in[3];
    const float* b_ih = (const float*)d_in[4];
    const float* b_hh = (const float*)d_in[5];
    float*       out  = (float*)d_out;

    zero_kernel<<<1, 1024>>>();
    len_kernel<<<N_SEQ / 8, 256>>>(x);
    scan_kernel<<<1, 1024>>>();
    scatter_kernel<<<N_SEQ / 256, 256>>>();
    gru_main<<<296, 192>>>(x, emb, w_ih, w_hh, b_ih, b_hh, out);
}

// round 4
// speedup vs baseline: 3.7126x; 1.3310x over previous
#include <cuda_runtime.h>

// GRU sequence encoder, round 4 (round 3 + h-zeroing fix).
// N=16384, L=512, ES=32, HS=64, gates [r|z|n] (torch order).
//
// P[v][g] = emb[v] . w_ih[g] + b_ih[g]  precomputed (32000 x 192, L2-resident).
// Recurrent loop does only the h-matvec + coalesced P-row gather.
// Counting-sort sequences by length (descending), 16 per CTA group.

#define N_SEQ   16384
#define L_SEQ   512
#define ES_DIM  32
#define HS_DIM  64
#define G3      192
#define WG      16
#define NGROUP  (N_SEQ / WG)   // 1024
#define NBUCKET 513
#define VOCAB   32000

__device__ float P[VOCAB * G3];          // 24.6 MB scratch: gx per token
__device__ int d_len[N_SEQ];
__device__ int d_bucket[NBUCKET];
__device__ int d_off[NBUCKET];
__device__ int d_sorted[N_SEQ];
__device__ int g_ctr;

#define FFMA2(acc, a, b) \
    asm("fma.rn.f32x2 %0, %1, %2, %0;" : "+l"(acc) : "l"(a), "l"(b))

__device__ __forceinline__ float pairsum(unsigned long long v) {
    return __uint_as_float((unsigned)v) + __uint_as_float((unsigned)(v >> 32));
}

// ---------------- prepass ----------------

__global__ void zero_kernel() {
    int t = threadIdx.x;
    if (t < NBUCKET) d_bucket[t] = 0;
    if (t == NBUCKET) g_ctr = 0;
}

#define LEN_CTAS 2048
#define P_ROWS_PER_CTA 64

__global__ void len_pre_kernel(const int* __restrict__ x,
                               const float* __restrict__ emb,
                               const float* __restrict__ w_ih,
                               const float* __restrict__ b_ih)
{
    if (blockIdx.x < LEN_CTAS) {
        // one warp per sequence: count nonzero tokens
        int seq  = blockIdx.x * 8 + (threadIdx.x >> 5);
        int lane = threadIdx.x & 31;
        const int4* row = reinterpret_cast<const int4*>(x + (long)seq * L_SEQ);
        int c = 0;
        #pragma unroll
        for (int k = 0; k < 4; k++) {
            int4 v = row[lane + 32 * k];
            c += (v.x != 0) + (v.y != 0) + (v.z != 0) + (v.w != 0);
        }
        #pragma unroll
        for (int off = 16; off > 0; off >>= 1) c += __shfl_xor_sync(~0u, c, off);
        if (lane == 0) {
            d_len[seq] = c;
            atomicAdd(&d_bucket[c], 1);
        }
    } else {
        // P precompute: thread j owns gate row j; 64 vocab rows per CTA
        int j = threadIdx.x;
        if (j >= G3) return;
        float w[ES_DIM];
        {
            const float4* wr = reinterpret_cast<const float4*>(w_ih + (long)j * ES_DIM);
            #pragma unroll
            for (int k = 0; k < ES_DIM / 4; k++) {
                float4 v = wr[k];
                w[4*k+0] = v.x; w[4*k+1] = v.y; w[4*k+2] = v.z; w[4*k+3] = v.w;
            }
        }
        const float bj = b_ih[j];
        int v0 = (blockIdx.x - LEN_CTAS) * P_ROWS_PER_CTA;
        for (int v = v0; v < v0 + P_ROWS_PER_CTA && v < VOCAB; v++) {
            const float4* er = reinterpret_cast<const float4*>(emb + (long)v * ES_DIM);
            float acc = bj;
            #pragma unroll
            for (int k = 0; k < ES_DIM / 4; k++) {
                float4 e = __ldg(&er[k]);   // broadcast across CTA, L1-hot
                acc = fmaf(w[4*k+0], e.x, acc);
                acc = fmaf(w[4*k+1], e.y, acc);
                acc = fmaf(w[4*k+2], e.z, acc);
                acc = fmaf(w[4*k+3], e.w, acc);
            }
            P[(long)v * G3 + j] = acc;
        }
    }
}

// single CTA: suffix scan (descending) + scatter
__global__ void scan_scatter_kernel() {
    __shared__ int sb[NBUCKET], so[NBUCKET];
    int t = threadIdx.x;
    for (int i = t; i < NBUCKET; i += blockDim.x) sb[i] = d_bucket[i];
    __syncthreads();
    if (t == 0) {
        int run = 0;
        for (int l = NBUCKET - 1; l >= 0; l--) { so[l] = run; run += sb[l]; }
    }
    __syncthreads();
    for (int i = t; i < NBUCKET; i += blockDim.x) d_off[i] = so[i];
    __syncthreads();
    for (int seq = t; seq < N_SEQ; seq += blockDim.x) {
        int l = d_len[seq];
        int pos = atomicAdd(&d_off[l], 1);
        d_sorted[pos] = seq;
    }
}

// ---------------- main ----------------

__launch_bounds__(192, 2)
__global__ void gru_main(const int*   __restrict__ x,
                         const float* __restrict__ w_hh,
                         const float* __restrict__ b_hh,
                         float*       __restrict__ out)
{
    __shared__ float  gx[2][WG][G3];        // 24 KB: gathered P rows (dbl-buf)
    __shared__ float  gate[3][WG][HS_DIM];  // 12 KB: r_h, z_h, hn
    __shared__ float4 h4[WG][HS_DIM / 4];   //  4 KB: hidden states
    __shared__ int    seq_sm[WG], len_sm[WG], gid_sm;

    const int j = threadIdx.x;              // stacked gate row 0..191
    const int i = j & 63;
    const int gsel = j >> 6;

    // recurrent weight row in registers, packed in 64-bit pairs
    ulonglong2 whh[HS_DIM / 4];
    {
        const ulonglong2* wp = reinterpret_cast<const ulonglong2*>(w_hh + (long)j * HS_DIM);
        #pragma unroll
        for (int k = 0; k < HS_DIM / 4; k++) whh[k] = wp[k];
    }
    const float bhh = b_hh[j];

    while (true) {
        if (j == 0) gid_sm = atomicAdd(&g_ctr, 1);
        __syncthreads();
        const int g = gid_sm;
        if (g >= NGROUP) break;

        if (j < WG) {
            int s = d_sorted[g * WG + j];
            seq_sm[j] = s;
            len_sm[j] = d_len[s];
        }
        // zero hidden states: 256 float4 slots over 192 threads (FIX: strided)
        for (int u = j; u < WG * (HS_DIM / 4); u += 192) {
            reinterpret_cast<float4*>(h4)[u] = make_float4(0.f, 0.f, 0.f, 0.f);
        }
        __syncthreads();

        const int maxlen = len_sm[0];       // descending sort
        int xoff[WG];
        #pragma unroll
        for (int s = 0; s < WG; s++) xoff[s] = seq_sm[s] * L_SEQ;

        if (maxlen > 0) {
            // prologue: gather gx(0)
            #pragma unroll
            for (int s = 0; s < WG; s++) {
                int tok = __ldg(&x[xoff[s]]);          // broadcast
                gx[0][s][j] = __ldg(&P[(long)tok * G3 + j]);
            }
            __syncthreads();

            int p = 0;
            for (int t = 0; t < maxlen; t++) {
                // prefetch gx(t+1) into regs (overlaps matvec)
                float gnext[WG];
                {
                    int tn = (t + 1 < L_SEQ) ? t + 1 : L_SEQ - 1;
                    #pragma unroll
                    for (int s = 0; s < WG; s++) {
                        int tok = __ldg(&x[xoff[s] + tn]);   // 0-pad -> P row 0
                        gnext[s] = __ldg(&P[(long)tok * G3 + j]);
                    }
                }

                // h-matvec: gate row j for 16 sequences
                #pragma unroll
                for (int s = 0; s < WG; s++) {
                    unsigned long long ah = 0ull;
                    const ulonglong2* hp = reinterpret_cast<const ulonglong2*>(&h4[s][0]);
                    #pragma unroll
                    for (int k = 0; k < HS_DIM / 4; k++) {
                        ulonglong2 hv = hp[k];
                        FFMA2(ah, whh[k].x, hv.x);
                        FFMA2(ah, whh[k].y, hv.y);
                    }
                    gate[gsel][s][i] = pairsum(ah) + bhh;
                }
                __syncthreads();   // gates ready; h reads done

                // stash prefetched gx for next step (other buffer)
                #pragma unroll
                for (int s = 0; s < WG; s++) gx[1 - p][s][j] = gnext[s];

                // update: 1024 h-elements over 192 threads
                #pragma unroll
                for (int q = 0; q < 6; q++) {
                    int u = j + 192 * q;
                    if (u < WG * HS_DIM) {
                        int s = u >> 6, ii = u & 63;
                        float rp = gx[p][s][ii]       + gate[0][s][ii];
                        float zp = gx[p][s][64 + ii]  + gate[1][s][ii];
                        float xn = gx[p][s][128 + ii];
                        float hn = gate[2][s][ii];
                        float r  = __fdividef(1.0f, 1.0f + __expf(-rp));
                        float z  = __fdividef(1.0f, 1.0f + __expf(-zp));
                        float a  = fmaf(r, hn, xn);
                        float ng = 1.0f - __fdividef(2.0f, __expf(2.0f * a) + 1.0f);
                        float* hptr = reinterpret_cast<float*>(h4[s]) + ii;
                        float ho = *hptr;
                        float hnew = fmaf(z, ho - ng, ng);
                        *hptr = (t < len_sm[s]) ? hnew : ho;
                    }
                }
                __syncthreads();   // h + gx(t+1) published
                p ^= 1;
            }
        } else {
            __syncthreads();       // h zeros visible
        }

        // write outputs
        #pragma unroll
        for (int q = 0; q < 6; q++) {
            int u = j + 192 * q;
            if (u < WG * HS_DIM) {
                int s = u >> 6, ii = u & 63;
                out[(long)seq_sm[s] * HS_DIM + ii] =
                    reinterpret_cast<const float*>(h4[s])[ii];
            }
        }
        // next claim barrier orders smem reuse
    }
}

extern "C" void kernel_launch(void* const* d_in, const int* in_sizes, int n_in,
                              void* d_out, int out_size)
{
    const int*   x    = (const int*)  d_in[0];
    const float* emb  = (const float*)d_in[1];
    const float* w_ih = (const float*)d_in[2];
    const float* w_hh = (const float*)d_in[3];
    const float* b_ih = (const float*)d_in[4];
    const float* b_hh = (const float*)d_in[5];
    float*       out  = (float*)d_out;

    zero_kernel<<<1, 1024>>>();
    len_pre_kernel<<<LEN_CTAS + (VOCAB + P_ROWS_PER_CTA - 1) / P_ROWS_PER_CTA, 256>>>(
        x, emb, w_ih, b_ih);
    scan_scatter_kernel<<<1, 256>>>();
    gru_main<<<296, 192>>>(x, w_hh, b_hh, out);
}

// round 5
// speedup vs baseline: 3.7135x; 1.0002x over previous
#include <cuda_runtime.h>

// GRU sequence encoder, round 4 (round 3 + h-zeroing fix).
// N=16384, L=512, ES=32, HS=64, gates [r|z|n] (torch order).
//
// P[v][g] = emb[v] . w_ih[g] + b_ih[g]  precomputed (32000 x 192, L2-resident).
// Recurrent loop does only the h-matvec + coalesced P-row gather.
// Counting-sort sequences by length (descending), 16 per CTA group.

#define N_SEQ   16384
#define L_SEQ   512
#define ES_DIM  32
#define HS_DIM  64
#define G3      192
#define WG      16
#define NGROUP  (N_SEQ / WG)   // 1024
#define NBUCKET 513
#define VOCAB   32000

__device__ float P[VOCAB * G3];          // 24.6 MB scratch: gx per token
__device__ int d_len[N_SEQ];
__device__ int d_bucket[NBUCKET];
__device__ int d_off[NBUCKET];
__device__ int d_sorted[N_SEQ];
__device__ int g_ctr;

#define FFMA2(acc, a, b) \
    asm("fma.rn.f32x2 %0, %1, %2, %0;" : "+l"(acc) : "l"(a), "l"(b))

__device__ __forceinline__ float pairsum(unsigned long long v) {
    return __uint_as_float((unsigned)v) + __uint_as_float((unsigned)(v >> 32));
}

// ---------------- prepass ----------------

__global__ void zero_kernel() {
    int t = threadIdx.x;
    if (t < NBUCKET) d_bucket[t] = 0;
    if (t == NBUCKET) g_ctr = 0;
}

#define LEN_CTAS 2048
#define P_ROWS_PER_CTA 64

__global__ void len_pre_kernel(const int* __restrict__ x,
                               const float* __restrict__ emb,
                               const float* __restrict__ w_ih,
                               const float* __restrict__ b_ih)
{
    if (blockIdx.x < LEN_CTAS) {
        // one warp per sequence: count nonzero tokens
        int seq  = blockIdx.x * 8 + (threadIdx.x >> 5);
        int lane = threadIdx.x & 31;
        const int4* row = reinterpret_cast<const int4*>(x + (long)seq * L_SEQ);
        int c = 0;
        #pragma unroll
        for (int k = 0; k < 4; k++) {
            int4 v = row[lane + 32 * k];
            c += (v.x != 0) + (v.y != 0) + (v.z != 0) + (v.w != 0);
        }
        #pragma unroll
        for (int off = 16; off > 0; off >>= 1) c += __shfl_xor_sync(~0u, c, off);
        if (lane == 0) {
            d_len[seq] = c;
            atomicAdd(&d_bucket[c], 1);
        }
    } else {
        // P precompute: thread j owns gate row j; 64 vocab rows per CTA
        int j = threadIdx.x;
        if (j >= G3) return;
        float w[ES_DIM];
        {
            const float4* wr = reinterpret_cast<const float4*>(w_ih + (long)j * ES_DIM);
            #pragma unroll
            for (int k = 0; k < ES_DIM / 4; k++) {
                float4 v = wr[k];
                w[4*k+0] = v.x; w[4*k+1] = v.y; w[4*k+2] = v.z; w[4*k+3] = v.w;
            }
        }
        const float bj = b_ih[j];
        int v0 = (blockIdx.x - LEN_CTAS) * P_ROWS_PER_CTA;
        for (int v = v0; v < v0 + P_ROWS_PER_CTA && v < VOCAB; v++) {
            const float4* er = reinterpret_cast<const float4*>(emb + (long)v * ES_DIM);
            float acc = bj;
            #pragma unroll
            for (int k = 0; k < ES_DIM / 4; k++) {
                float4 e = __ldg(&er[k]);   // broadcast across CTA, L1-hot
                acc = fmaf(w[4*k+0], e.x, acc);
                acc = fmaf(w[4*k+1], e.y, acc);
                acc = fmaf(w[4*k+2], e.z, acc);
                acc = fmaf(w[4*k+3], e.w, acc);
            }
            P[(long)v * G3 + j] = acc;
        }
    }
}

// single CTA: suffix scan (descending) + scatter
__global__ void scan_scatter_kernel() {
    __shared__ int sb[NBUCKET], so[NBUCKET];
    int t = threadIdx.x;
    for (int i = t; i < NBUCKET; i += blockDim.x) sb[i] = d_bucket[i];
    __syncthreads();
    if (t == 0) {
        int run = 0;
        for (int l = NBUCKET - 1; l >= 0; l--) { so[l] = run; run += sb[l]; }
    }
    __syncthreads();
    for (int i = t; i < NBUCKET; i += blockDim.x) d_off[i] = so[i];
    __syncthreads();
    for (int seq = t; seq < N_SEQ; seq += blockDim.x) {
        int l = d_len[seq];
        int pos = atomicAdd(&d_off[l], 1);
        d_sorted[pos] = seq;
    }
}

// ---------------- main ----------------

__launch_bounds__(192, 2)
__global__ void gru_main(const int*   __restrict__ x,
                         const float* __restrict__ w_hh,
                         const float* __restrict__ b_hh,
                         float*       __restrict__ out)
{
    __shared__ float  gx[2][WG][G3];        // 24 KB: gathered P rows (dbl-buf)
    __shared__ float  gate[3][WG][HS_DIM];  // 12 KB: r_h, z_h, hn
    __shared__ float4 h4[WG][HS_DIM / 4];   //  4 KB: hidden states
    __shared__ int    seq_sm[WG], len_sm[WG], gid_sm;

    const int j = threadIdx.x;              // stacked gate row 0..191
    const int i = j & 63;
    const int gsel = j >> 6;

    // recurrent weight row in registers, packed in 64-bit pairs
    ulonglong2 whh[HS_DIM / 4];
    {
        const ulonglong2* wp = reinterpret_cast<const ulonglong2*>(w_hh + (long)j * HS_DIM);
        #pragma unroll
        for (int k = 0; k < HS_DIM / 4; k++) whh[k] = wp[k];
    }
    const float bhh = b_hh[j];

    while (true) {
        if (j == 0) gid_sm = atomicAdd(&g_ctr, 1);
        __syncthreads();
        const int g = gid_sm;
        if (g >= NGROUP) break;

        if (j < WG) {
            int s = d_sorted[g * WG + j];
            seq_sm[j] = s;
            len_sm[j] = d_len[s];
        }
        // zero hidden states: 256 float4 slots over 192 threads (FIX: strided)
        for (int u = j; u < WG * (HS_DIM / 4); u += 192) {
            reinterpret_cast<float4*>(h4)[u] = make_float4(0.f, 0.f, 0.f, 0.f);
        }
        __syncthreads();

        const int maxlen = len_sm[0];       // descending sort
        int xoff[WG];
        #pragma unroll
        for (int s = 0; s < WG; s++) xoff[s] = seq_sm[s] * L_SEQ;

        if (maxlen > 0) {
            // prologue: gather gx(0)
            #pragma unroll
            for (int s = 0; s < WG; s++) {
                int tok = __ldg(&x[xoff[s]]);          // broadcast
                gx[0][s][j] = __ldg(&P[(long)tok * G3 + j]);
            }
            __syncthreads();

            int p = 0;
            for (int t = 0; t < maxlen; t++) {
                // prefetch gx(t+1) into regs (overlaps matvec)
                float gnext[WG];
                {
                    int tn = (t + 1 < L_SEQ) ? t + 1 : L_SEQ - 1;
                    #pragma unroll
                    for (int s = 0; s < WG; s++) {
                        int tok = __ldg(&x[xoff[s] + tn]);   // 0-pad -> P row 0
                        gnext[s] = __ldg(&P[(long)tok * G3 + j]);
                    }
                }

                // h-matvec: gate row j for 16 sequences
                #pragma unroll
                for (int s = 0; s < WG; s++) {
                    unsigned long long ah = 0ull;
                    const ulonglong2* hp = reinterpret_cast<const ulonglong2*>(&h4[s][0]);
                    #pragma unroll
                    for (int k = 0; k < HS_DIM / 4; k++) {
                        ulonglong2 hv = hp[k];
                        FFMA2(ah, whh[k].x, hv.x);
                        FFMA2(ah, whh[k].y, hv.y);
                    }
                    gate[gsel][s][i] = pairsum(ah) + bhh;
                }
                __syncthreads();   // gates ready; h reads done

                // stash prefetched gx for next step (other buffer)
                #pragma unroll
                for (int s = 0; s < WG; s++) gx[1 - p][s][j] = gnext[s];

                // update: 1024 h-elements over 192 threads
                #pragma unroll
                for (int q = 0; q < 6; q++) {
                    int u = j + 192 * q;
                    if (u < WG * HS_DIM) {
                        int s = u >> 6, ii = u & 63;
                        float rp = gx[p][s][ii]       + gate[0][s][ii];
                        float zp = gx[p][s][64 + ii]  + gate[1][s][ii];
                        float xn = gx[p][s][128 + ii];
                        float hn = gate[2][s][ii];
                        float r  = __fdividef(1.0f, 1.0f + __expf(-rp));
                        float z  = __fdividef(1.0f, 1.0f + __expf(-zp));
                        float a  = fmaf(r, hn, xn);
                        float ng = 1.0f - __fdividef(2.0f, __expf(2.0f * a) + 1.0f);
                        float* hptr = reinterpret_cast<float*>(h4[s]) + ii;
                        float ho = *hptr;
                        float hnew = fmaf(z, ho - ng, ng);
                        *hptr = (t < len_sm[s]) ? hnew : ho;
                    }
                }
                __syncthreads();   // h + gx(t+1) published
                p ^= 1;
            }
        } else {
            __syncthreads();       // h zeros visible
        }

        // write outputs
        #pragma unroll
        for (int q = 0; q < 6; q++) {
            int u = j + 192 * q;
            if (u < WG * HS_DIM) {
                int s = u >> 6, ii = u & 63;
                out[(long)seq_sm[s] * HS_DIM + ii] =
                    reinterpret_cast<const float*>(h4[s])[ii];
            }
        }
        // next claim barrier orders smem reuse
    }
}

extern "C" void kernel_launch(void* const* d_in, const int* in_sizes, int n_in,
                              void* d_out, int out_size)
{
    const int*   x    = (const int*)  d_in[0];
    const float* emb  = (const float*)d_in[1];
    const float* w_ih = (const float*)d_in[2];
    const float* w_hh = (const float*)d_in[3];
    const float* b_ih = (const float*)d_in[4];
    const float* b_hh = (const float*)d_in[5];
    float*       out  = (float*)d_out;

    zero_kernel<<<1, 1024>>>();
    len_pre_kernel<<<LEN_CTAS + (VOCAB + P_ROWS_PER_CTA - 1) / P_ROWS_PER_CTA, 256>>>(
        x, emb, w_ih, b_ih);
    scan_scatter_kernel<<<1, 256>>>();
    gru_main<<<296, 192>>>(x, w_hh, b_hh, out);
}